// round 7
// baseline (speedup 1.0000x reference)
#include <cuda_runtime.h>
#include <cstdint>

#define N_NODES   100000
#define N_EDGES   1600000
#define D         32
#define OUT_FEAT  32
#define CAP       256     // max edges per node bucket (dataset max deg ~45)

// Device-global scratch (zero-init at load; cnt re-zeroed by final each call)
__device__ int   g_cnt[N_NODES];
__device__ int   g_bucket[(size_t)N_NODES * CAP];        // 102.4 MB edge ids
__device__ __align__(16) float g_partial[N_NODES * D];   // node@W1[0:32] + gb

#define TPB  128

// K1: place blocks first, then partial-MLP blocks
#define E_PER_THREAD 4
#define PLACE_BLOCKS (N_EDGES / (TPB * E_PER_THREAD))    // 3125 exactly
#define NBP  128
#define P_BLOCKS     ((N_NODES + NBP - 1) / NBP)         // 782
#define XSTR 33
#define SMEM1_FLOATS (NBP * XSTR + 32 * 32 + 32)
#define SMEM2_FLOATS (NBP * XSTR + 32 * 32 + 32 * 32 + 32)

// ---------------------------------------------------------------------------
// Kernel 1 (fused): blocks [0, PLACE_BLOCKS) bucket edge ids by receiver
// (1.6M atomicAdd-return lanes — 8x fewer atomic lanes than payload scatter);
// blocks after that compute P = node@W1[0:32] + (b1 + global@W1[64:96]).
// ---------------------------------------------------------------------------
__global__ __launch_bounds__(TPB) void place_partial_kernel(
    const int* __restrict__ receivers,
    const float* __restrict__ node_attr,
    const float* __restrict__ global_attr,
    const float* __restrict__ W1,
    const float* __restrict__ b1)
{
    const int tid = threadIdx.x;

    if (blockIdx.x < PLACE_BLOCKS) {
        const int e0 = blockIdx.x * (TPB * E_PER_THREAD) + tid;
        int r[E_PER_THREAD];
        #pragma unroll
        for (int t = 0; t < E_PER_THREAD; t++)
            r[t] = receivers[e0 + TPB * t];
        #pragma unroll
        for (int t = 0; t < E_PER_THREAD; t++) {
            int e = e0 + TPB * t;
            if ((unsigned)r[t] < N_NODES) {
                int pos = atomicAdd(&g_cnt[r[t]], 1);
                if (pos < CAP)
                    g_bucket[(size_t)r[t] * CAP + pos] = e;
            }
        }
        return;
    }

    // ---------------- partial-MLP path (4 nodes x 8 cols per thread) -------
    extern __shared__ float smem[];
    float* xs  = smem;                  // [NBP][XSTR]
    float* w1s = xs + NBP * XSTR;       // [32][32]  W1 rows 0..31
    float* gb  = w1s + 32 * 32;         // [32]

    const int cg   = tid & 3;
    const int q    = tid >> 2;
    const int base = (blockIdx.x - PLACE_BLOCKS) * NBP;
    const int nvalid = min(NBP, N_NODES - base);
    const bool full  = (nvalid == NBP);

    {
        const float4* w1v = reinterpret_cast<const float4*>(W1);
        float4 a0 = w1v[tid], a1 = w1v[tid + 128];
        reinterpret_cast<float4*>(w1s)[tid]       = a0;
        reinterpret_cast<float4*>(w1s)[tid + 128] = a1;
    }
    if (tid < 32) {
        float acc = b1[tid];
        #pragma unroll
        for (int k = 0; k < D; k++)
            acc = fmaf(global_attr[k], W1[(64 + k) * 32 + tid], acc);
        gb[tid] = acc;
    }
    {
        const float4* nav = reinterpret_cast<const float4*>(node_attr) + (size_t)base * 8;
        float4 va[8];
        #pragma unroll
        for (int t = 0; t < 8; t++) {
            int idx = tid + 128 * t;
            if (full || (idx >> 3) < nvalid) va[t] = nav[idx];
            else va[t] = make_float4(0, 0, 0, 0);
        }
        #pragma unroll
        for (int t = 0; t < 8; t++) {
            int idx = tid + 128 * t;
            int n = idx >> 3, c = idx & 7;
            float* p = &xs[n * XSTR + 4 * c];
            p[0] = va[t].x; p[1] = va[t].y; p[2] = va[t].z; p[3] = va[t].w;
        }
    }
    __syncthreads();

    float acc[4][8];
    #pragma unroll
    for (int j = 0; j < 4; j++)
        #pragma unroll
        for (int m = 0; m < 8; m++) acc[j][m] = gb[cg * 8 + m];

    const float* x0 = &xs[(4 * q + 0) * XSTR];
    const float* x1 = &xs[(4 * q + 1) * XSTR];
    const float* x2 = &xs[(4 * q + 2) * XSTR];
    const float* x3 = &xs[(4 * q + 3) * XSTR];

    #pragma unroll 4
    for (int k = 0; k < 32; k++) {
        float4 wa = *reinterpret_cast<const float4*>(&w1s[k * 32 + cg * 8]);
        float4 wb = *reinterpret_cast<const float4*>(&w1s[k * 32 + cg * 8 + 4]);
        float w[8] = {wa.x, wa.y, wa.z, wa.w, wb.x, wb.y, wb.z, wb.w};
        float xv[4] = {x0[k], x1[k], x2[k], x3[k]};
        #pragma unroll
        for (int j = 0; j < 4; j++)
            #pragma unroll
            for (int m = 0; m < 8; m++)
                acc[j][m] = fmaf(xv[j], w[m], acc[j][m]);
    }

    #pragma unroll
    for (int j = 0; j < 4; j++) {
        int n = 4 * q + j;
        if (n < nvalid) {
            float* dst = g_partial + (size_t)(base + n) * D + cg * 8;
            reinterpret_cast<float4*>(dst)[0] =
                make_float4(acc[j][0], acc[j][1], acc[j][2], acc[j][3]);
            reinterpret_cast<float4*>(dst)[1] =
                make_float4(acc[j][4], acc[j][5], acc[j][6], acc[j][7]);
        }
    }
}

// ---------------------------------------------------------------------------
// Kernel 2: gather + final MLP. Per 128-node block:
//   gather: 8 threads/node sum that node's bucketed edge rows (float4 chunk
//           each) straight from edge_attr — no atomics, DRAM-streaming.
//   then:   out = relu(P + agg @ W1[32:64]) @ W2 + b2  (4x8 register tiles).
// Re-zeroes g_cnt for the next call.
// ---------------------------------------------------------------------------
__global__ __launch_bounds__(TPB) void gather_mlp_kernel(
    const float* __restrict__ edge_attr,
    const float* __restrict__ W1,
    const float* __restrict__ W2, const float* __restrict__ b2,
    float* __restrict__ out)
{
    extern __shared__ float smem[];
    float* xs  = smem;                 // [NBP][XSTR] agg; reused as ht
    float* w1s = xs + NBP * XSTR;      // [32][32]  W1 rows 32..63
    float* w2s = w1s + 32 * 32;        // [32][32]
    float* b2s = w2s + 32 * 32;        // [32]

    const int tid  = threadIdx.x;
    const int cg   = tid & 3;
    const int q    = tid >> 2;
    const int base = blockIdx.x * NBP;
    const int nvalid = min(NBP, N_NODES - base);
    const bool full  = (nvalid == NBP);

    // stage W1 rows 32..63 (f4 offset 256) and W2
    {
        const float4* w1v = reinterpret_cast<const float4*>(W1);
        const float4* w2v = reinterpret_cast<const float4*>(W2);
        float4 a0 = w1v[256 + tid], a1 = w1v[256 + tid + 128];
        float4 c0 = w2v[tid],       c1 = w2v[tid + 128];
        reinterpret_cast<float4*>(w1s)[tid]       = a0;
        reinterpret_cast<float4*>(w1s)[tid + 128] = a1;
        reinterpret_cast<float4*>(w2s)[tid]       = c0;
        reinterpret_cast<float4*>(w2s)[tid + 128] = c1;
    }
    if (tid < 32) b2s[tid] = b2[tid];

    // ---- gather: 8 passes x 16 nodes; 8 threads per node (f4 chunk c) ----
    {
        const float4* ea4 = reinterpret_cast<const float4*>(edge_attr);
        const int c  = tid & 7;
        const int nl = tid >> 3;           // 0..15
        #pragma unroll
        for (int pass = 0; pass < 8; pass++) {
            int n = pass * 16 + nl;
            float4 a = make_float4(0.f, 0.f, 0.f, 0.f);
            if (n < nvalid) {
                int node = base + n;
                int count = g_cnt[node];
                if (count > CAP) count = CAP;
                const int* bk = g_bucket + (size_t)node * CAP;
                int i = 0;
                for (; i + 4 <= count; i += 4) {
                    int id0 = bk[i], id1 = bk[i + 1], id2 = bk[i + 2], id3 = bk[i + 3];
                    float4 v0 = ea4[(size_t)id0 * 8 + c];
                    float4 v1 = ea4[(size_t)id1 * 8 + c];
                    float4 v2 = ea4[(size_t)id2 * 8 + c];
                    float4 v3 = ea4[(size_t)id3 * 8 + c];
                    a.x += v0.x + v1.x + v2.x + v3.x;
                    a.y += v0.y + v1.y + v2.y + v3.y;
                    a.z += v0.z + v1.z + v2.z + v3.z;
                    a.w += v0.w + v1.w + v2.w + v3.w;
                }
                for (; i < count; i++) {
                    float4 v = ea4[(size_t)bk[i] * 8 + c];
                    a.x += v.x; a.y += v.y; a.z += v.z; a.w += v.w;
                }
                if (c == 0) g_cnt[node] = 0;   // reset for next call
            }
            float* p = &xs[n * XSTR + 4 * c];
            p[0] = a.x; p[1] = a.y; p[2] = a.z; p[3] = a.w;
        }
    }

    // load this thread's P tile (4 nodes x 8 cols)
    float acc[4][8];
    {
        const float4* pv = reinterpret_cast<const float4*>(g_partial) + (size_t)base * 8;
        #pragma unroll
        for (int j = 0; j < 4; j++) {
            int n = 4 * q + j;
            float4 pa, pb;
            if (full || n < nvalid) {
                pa = pv[n * 8 + cg * 2];
                pb = pv[n * 8 + cg * 2 + 1];
            } else { pa = make_float4(0,0,0,0); pb = pa; }
            acc[j][0] = pa.x; acc[j][1] = pa.y; acc[j][2] = pa.z; acc[j][3] = pa.w;
            acc[j][4] = pb.x; acc[j][5] = pb.y; acc[j][6] = pb.z; acc[j][7] = pb.w;
        }
    }
    __syncthreads();

    // layer 1 remainder: += agg @ W1[32:64]
    const float* x0 = &xs[(4 * q + 0) * XSTR];
    const float* x1 = &xs[(4 * q + 1) * XSTR];
    const float* x2 = &xs[(4 * q + 2) * XSTR];
    const float* x3 = &xs[(4 * q + 3) * XSTR];

    #pragma unroll 4
    for (int k = 0; k < 32; k++) {
        float4 wa = *reinterpret_cast<const float4*>(&w1s[k * 32 + cg * 8]);
        float4 wb = *reinterpret_cast<const float4*>(&w1s[k * 32 + cg * 8 + 4]);
        float w[8] = {wa.x, wa.y, wa.z, wa.w, wb.x, wb.y, wb.z, wb.w};
        float xv[4] = {x0[k], x1[k], x2[k], x3[k]};
        #pragma unroll
        for (int j = 0; j < 4; j++)
            #pragma unroll
            for (int m = 0; m < 8; m++)
                acc[j][m] = fmaf(xv[j], w[m], acc[j][m]);
    }

    // relu + round-trip h through smem (reuse xs region)
    __syncthreads();
    float* ht = xs;
    #pragma unroll
    for (int j = 0; j < 4; j++) {
        int n = 4 * q + j;
        #pragma unroll
        for (int m = 0; m < 8; m++)
            ht[n * XSTR + cg * 8 + m] = fmaxf(acc[j][m], 0.f);
    }
    __syncthreads();

    // layer 2
    float o[4][8];
    #pragma unroll
    for (int j = 0; j < 4; j++)
        #pragma unroll
        for (int m = 0; m < 8; m++) o[j][m] = b2s[cg * 8 + m];

    const float* h0 = &ht[(4 * q + 0) * XSTR];
    const float* h1 = &ht[(4 * q + 1) * XSTR];
    const float* h2 = &ht[(4 * q + 2) * XSTR];
    const float* h3 = &ht[(4 * q + 3) * XSTR];

    #pragma unroll 4
    for (int i = 0; i < 32; i++) {
        float4 wa = *reinterpret_cast<const float4*>(&w2s[i * 32 + cg * 8]);
        float4 wb = *reinterpret_cast<const float4*>(&w2s[i * 32 + cg * 8 + 4]);
        float w[8] = {wa.x, wa.y, wa.z, wa.w, wb.x, wb.y, wb.z, wb.w};
        float hv[4] = {h0[i], h1[i], h2[i], h3[i]};
        #pragma unroll
        for (int j = 0; j < 4; j++)
            #pragma unroll
            for (int m = 0; m < 8; m++)
                o[j][m] = fmaf(hv[j], w[m], o[j][m]);
    }

    #pragma unroll
    for (int j = 0; j < 4; j++) {
        int n = 4 * q + j;
        if (n < nvalid) {
            float* dst = out + (size_t)(base + n) * OUT_FEAT + cg * 8;
            reinterpret_cast<float4*>(dst)[0] =
                make_float4(o[j][0], o[j][1], o[j][2], o[j][3]);
            reinterpret_cast<float4*>(dst)[1] =
                make_float4(o[j][4], o[j][5], o[j][6], o[j][7]);
        }
    }
}

// ---------------------------------------------------------------------------
// Launch.
// ---------------------------------------------------------------------------
extern "C" void kernel_launch(void* const* d_in, const int* in_sizes, int n_in,
                              void* d_out, int out_size) {
    const float* node_attr   = (const float*)d_in[0];
    const int*   edge_index  = (const int*)d_in[1];
    const float* edge_attr   = (const float*)d_in[2];
    const float* global_attr = (const float*)d_in[3];
    const float* W1          = (const float*)d_in[4];
    const float* b1          = (const float*)d_in[5];
    const float* W2          = (const float*)d_in[6];
    const float* b2          = (const float*)d_in[7];
    float*       out         = (float*)d_out;

    const int* receivers = edge_index + N_EDGES;

    // 1) bucket edge ids by receiver (+ partial MLP in tail).
    //    g_cnt is zero: load-time init, re-zeroed by gather_mlp every call.
    {
        size_t smem1 = SMEM1_FLOATS * sizeof(float);
        cudaFuncSetAttribute(place_partial_kernel,
                             cudaFuncAttributeMaxDynamicSharedMemorySize,
                             (int)smem1);
        place_partial_kernel<<<PLACE_BLOCKS + P_BLOCKS, TPB, smem1>>>(
            receivers, node_attr, global_attr, W1, b1);
    }

    // 2) gather + final MLP
    {
        size_t smem2 = SMEM2_FLOATS * sizeof(float);
        cudaFuncSetAttribute(gather_mlp_kernel,
                             cudaFuncAttributeMaxDynamicSharedMemorySize,
                             (int)smem2);
        gather_mlp_kernel<<<P_BLOCKS, TPB, smem2>>>(edge_attr, W1, W2, b2, out);
    }
    (void)in_sizes; (void)n_in; (void)out_size;
}